// round 9
// baseline (speedup 1.0000x reference)
#include <cuda_runtime.h>
#include <cuda_bf16.h>
#include <math.h>
#include <stdint.h>

#define TOKS    8192
#define DMODEL  1024
#define FEXP    512
#define NEXP    16
#define NROUTED 14
#define KROUTE  4
#define KSEL    6

#define BM 64
#define BN 64
#define BK 64
#define LDSE 72      // smem row stride in elements (64 + 8 pad) -> 144 bytes

// ---------------- device scratch (static globals, 16B aligned) --------------
__device__ __align__(16) int   g_cnt[NEXP];
__device__ int   g_ok;
__device__ __align__(16) int   g_tok[NEXP * TOKS];
__device__ __align__(16) float g_aff[NEXP * TOKS];

__device__ __align__(16) __nv_bfloat16 g_x_hi[(size_t)TOKS * DMODEL];
__device__ __align__(16) __nv_bfloat16 g_x_lo[(size_t)TOKS * DMODEL];
__device__ __align__(16) __nv_bfloat16 g_k_hi[(size_t)NEXP * FEXP * DMODEL];  // keys^T [e][f][d]
__device__ __align__(16) __nv_bfloat16 g_k_lo[(size_t)NEXP * FEXP * DMODEL];
__device__ __align__(16) __nv_bfloat16 g_v_hi[(size_t)NEXP * DMODEL * FEXP];  // values^T [e][d][f]
__device__ __align__(16) __nv_bfloat16 g_v_lo[(size_t)NEXP * DMODEL * FEXP];
__device__ __align__(16) __nv_bfloat16 g_h_hi[(size_t)NEXP * TOKS * FEXP];    // silu(xK)*aff
__device__ __align__(16) __nv_bfloat16 g_h_lo[(size_t)NEXP * TOKS * FEXP];

__device__ __align__(16) float g_out_tc[(size_t)TOKS * DMODEL];               // TC result
__device__ __align__(16) float g_hf[(size_t)NEXP * TOKS * FEXP];              // fp32 fallback H

// ---------------- helpers ----------------------------------------------------
__device__ __forceinline__ uint32_t smem_u32(const void* p) {
    uint32_t a;
    asm("{ .reg .u64 t; cvta.to.shared.u64 t, %1; cvt.u32.u64 %0, t; }" : "=r"(a) : "l"(p));
    return a;
}
__device__ __forceinline__ void ldsm4(uint32_t* r, uint32_t addr) {
    asm volatile("ldmatrix.sync.aligned.m8n8.x4.shared.b16 {%0,%1,%2,%3}, [%4];"
        : "=r"(r[0]), "=r"(r[1]), "=r"(r[2]), "=r"(r[3]) : "r"(addr));
}
__device__ __forceinline__ void mma16816(float* c, const uint32_t* a,
                                         uint32_t b0, uint32_t b1) {
    asm volatile("mma.sync.aligned.m16n8k16.row.col.f32.bf16.bf16.f32 "
        "{%0,%1,%2,%3},{%4,%5,%6,%7},{%8,%9},{%0,%1,%2,%3};"
        : "+f"(c[0]), "+f"(c[1]), "+f"(c[2]), "+f"(c[3])
        : "r"(a[0]), "r"(a[1]), "r"(a[2]), "r"(a[3]), "r"(b0), "r"(b1));
}
__device__ __forceinline__ unsigned short bf16bits(float f) {
    __nv_bfloat16 b = __float2bfloat16(f);
    return *reinterpret_cast<unsigned short*>(&b);
}
__device__ __forceinline__ float bf16val(unsigned short u) {
    __nv_bfloat16 b = *reinterpret_cast<__nv_bfloat16*>(&u);
    return __bfloat162float(b);
}

// ---------------- utility kernels -------------------------------------------
__global__ void zero_out_kernel(float* out, int n) {
    int i = blockIdx.x * blockDim.x + threadIdx.x;
    if (i < n) out[i] = 0.f;
}
__global__ void zero_misc_kernel() {
    if (threadIdx.x < NEXP) g_cnt[threadIdx.x] = 0;
    if (threadIdx.x == 0) g_ok = 1;
}
__global__ void zero_tc_kernel() {
    int i = blockIdx.x * blockDim.x + threadIdx.x;
    if (i < TOKS * DMODEL) g_out_tc[i] = 0.f;
}

__global__ __launch_bounds__(256) void conv_x_kernel(const float* __restrict__ x) {
    int i = blockIdx.x * blockDim.x + threadIdx.x;
    if (i >= TOKS * DMODEL / 4) return;
    float4 v = reinterpret_cast<const float4*>(x)[i];
    ushort4 h, l;
    h.x = bf16bits(v.x); l.x = bf16bits(v.x - bf16val(h.x));
    h.y = bf16bits(v.y); l.y = bf16bits(v.y - bf16val(h.y));
    h.z = bf16bits(v.z); l.z = bf16bits(v.z - bf16val(h.z));
    h.w = bf16bits(v.w); l.w = bf16bits(v.w - bf16val(h.w));
    reinterpret_cast<ushort4*>(g_x_hi)[i] = h;
    reinterpret_cast<ushort4*>(g_x_lo)[i] = l;
}

// transpose + split: in [e][R][C] f32 -> out [e][C][R] bf16 hi/lo
__global__ __launch_bounds__(256) void conv_tr_kernel(
    const float* __restrict__ in, __nv_bfloat16* __restrict__ ohi,
    __nv_bfloat16* __restrict__ olo, int R, int C)
{
    __shared__ float ts[32][33];
    const int e  = blockIdx.z;
    const int c0 = blockIdx.x * 32;
    const int r0 = blockIdx.y * 32;
    const int tx = threadIdx.x, ty = threadIdx.y;
    const float* src = in + (size_t)e * R * C;
    #pragma unroll
    for (int i = ty; i < 32; i += 8)
        ts[i][tx] = src[(size_t)(r0 + i) * C + c0 + tx];
    __syncthreads();
    unsigned short* dh = reinterpret_cast<unsigned short*>(ohi) + (size_t)e * R * C;
    unsigned short* dl = reinterpret_cast<unsigned short*>(olo) + (size_t)e * R * C;
    #pragma unroll
    for (int i = ty; i < 32; i += 8) {
        float v = ts[tx][i];
        unsigned short h = bf16bits(v);
        unsigned short l = bf16bits(v - bf16val(h));
        size_t o = (size_t)(c0 + i) * R + r0 + tx;
        dh[o] = h; dl[o] = l;
    }
}

// ---------------- routing ---------------------------------------------------
__global__ __launch_bounds__(256) void routing_kernel(
    const float* __restrict__ sel_in,
    const float* __restrict__ expert_sel,
    const float* __restrict__ bias,
    float* __restrict__ out, int write_sel)
{
    const int t    = blockIdx.x;
    const int tid  = threadIdx.x;
    const int warp = tid >> 5, lane = tid & 31;
    __shared__ float logit[NEXP];

    const float* x = sel_in + (size_t)t * DMODEL;
    #pragma unroll
    for (int w = 0; w < 2; w++) {
        int e = warp * 2 + w;
        const float* wr = expert_sel + (size_t)e * DMODEL;
        float s = 0.f;
        for (int i = lane; i < DMODEL; i += 32) s += x[i] * wr[i];
        #pragma unroll
        for (int o = 16; o > 0; o >>= 1) s += __shfl_xor_sync(0xffffffffu, s, o);
        if (lane == 0) logit[e] = s;
    }
    __syncthreads();

    if (tid == 0) {
        float a[NEXP];
        #pragma unroll
        for (int e = 0; e < NEXP; e++) a[e] = 1.f / (1.f + expf(-logit[e]));

        int sel[KSEL]; float af[KSEL];
        bool taken[NROUTED];
        #pragma unroll
        for (int i = 0; i < NROUTED; i++) taken[i] = false;
        #pragma unroll
        for (int k = 0; k < KROUTE; k++) {
            float best = -1e30f; int bi = 0;
            for (int i = 0; i < NROUTED; i++) {
                float v = a[i] + bias[i];
                if (!taken[i] && v > best) { best = v; bi = i; }
            }
            taken[bi] = true; sel[k] = bi; af[k] = a[bi];
        }
        sel[4] = NROUTED;     af[4] = a[NROUTED];
        sel[5] = NROUTED + 1; af[5] = a[NROUTED + 1];

        #pragma unroll
        for (int k = 0; k < KSEL; k++) {
            int e   = sel[k];
            int pos = atomicAdd(&g_cnt[e], 1);
            g_tok[e * TOKS + pos] = t;
            g_aff[e * TOKS + pos] = af[k];
            if (write_sel)
                out[(size_t)TOKS * DMODEL + (size_t)t * KSEL + k] = (float)e;
        }
    }
}

// ---------------- mma.sync grouped GEMM (64x64x64, static smem) -------------
struct __align__(16) GemmSmem {
    int   toks[BM];
    float affs[BM];
    __nv_bfloat16 a_hi[BM * LDSE];
    __nv_bfloat16 a_lo[BM * LDSE];
    __nv_bfloat16 b_hi[BN * LDSE];
    __nv_bfloat16 b_lo[BN * LDSE];
};

__device__ __forceinline__ void store_stage(GemmSmem& s, const uint4* pf, int tid) {
    uint4* dst[4] = { (uint4*)s.a_hi, (uint4*)s.a_lo, (uint4*)s.b_hi, (uint4*)s.b_lo };
    #pragma unroll
    for (int it = 0; it < 8; it++) {
        int reg = it >> 1;
        int idx = tid + (it & 1) * 256;
        int r = idx >> 3, j = idx & 7;
        dst[reg][r * 9 + j] = pf[it];    // 9 uint4 per row (144B stride)
    }
}

__device__ __forceinline__ void mma_stage(
    const GemmSmem& s, int wm0, int wn0, int lane, float (&acc)[2][2][4])
{
    const int sub = lane >> 3, li = lane & 7;
    #pragma unroll
    for (int ks = 0; ks < 4; ks++) {
        uint32_t ah[2][4], al[2][4], bh[4], bl[4];
        #pragma unroll
        for (int mt = 0; mt < 2; mt++) {
            int row = wm0 + mt * 16 + (sub & 1) * 8 + li;
            int kel = ks * 16 + (sub >> 1) * 8;
            ldsm4(ah[mt], smem_u32(&s.a_hi[row * LDSE + kel]));
            ldsm4(al[mt], smem_u32(&s.a_lo[row * LDSE + kel]));
        }
        {
            int row = wn0 + (sub >> 1) * 8 + li;
            int kel = ks * 16 + (sub & 1) * 8;
            ldsm4(bh, smem_u32(&s.b_hi[row * LDSE + kel]));
            ldsm4(bl, smem_u32(&s.b_lo[row * LDSE + kel]));
        }
        #pragma unroll
        for (int mt = 0; mt < 2; mt++)
            #pragma unroll
            for (int n8 = 0; n8 < 2; n8++) {
                mma16816(acc[mt][n8], ah[mt], bh[n8 * 2], bh[n8 * 2 + 1]);
                mma16816(acc[mt][n8], ah[mt], bl[n8 * 2], bl[n8 * 2 + 1]);
                mma16816(acc[mt][n8], al[mt], bh[n8 * 2], bh[n8 * 2 + 1]);
            }
    }
}

// ---------------- TC GEMM 1: H = silu(gather(X) @ K_e^T) * aff --------------
__global__ __launch_bounds__(256, 2) void moe_gemm1() {
    const int e   = blockIdx.y;
    const int cnt = g_cnt[e];
    const int m0  = blockIdx.x * BM;
    if (m0 >= cnt) return;
    const int n0  = blockIdx.z * BN;

    __shared__ GemmSmem s;
    const int tid = threadIdx.x, wid = tid >> 5, lane = tid & 31;
    const int wm0 = (wid & 1) * 32, wn0 = (wid >> 1) * 16;

    if (tid < BM) {
        int mg = m0 + tid; bool v = mg < cnt;
        s.toks[tid] = v ? g_tok[e * TOKS + mg] : 0;
        s.affs[tid] = v ? g_aff[e * TOKS + mg] : 0.f;
    }
    __syncthreads();

    float acc[2][2][4];
    #pragma unroll
    for (int a = 0; a < 2; a++)
        #pragma unroll
        for (int b = 0; b < 2; b++)
            #pragma unroll
            for (int c = 0; c < 4; c++) acc[a][b][c] = 0.f;

    uint4 pf[8];
    #pragma unroll
    for (int it = 0; it < 8; it++) {
        int reg = it >> 1;
        int idx = tid + (it & 1) * 256;
        int r = idx >> 3, j = idx & 7;
        const __nv_bfloat16* src;
        if (reg < 2) src = (reg ? g_x_lo : g_x_hi) + (size_t)s.toks[r] * DMODEL + j * 8;
        else         src = (reg == 3 ? g_k_lo : g_k_hi) + ((size_t)e * FEXP + n0 + r) * DMODEL + j * 8;
        pf[it] = *reinterpret_cast<const uint4*>(src);
    }

    const int NC = DMODEL / BK;    // 16
    for (int c = 0; c < NC; c++) {
        __syncthreads();
        store_stage(s, pf, tid);
        __syncthreads();
        if (c + 1 < NC) {
            int k0 = (c + 1) * BK;
            #pragma unroll
            for (int it = 0; it < 8; it++) {
                int reg = it >> 1;
                int idx = tid + (it & 1) * 256;
                int r = idx >> 3, j = idx & 7;
                const __nv_bfloat16* src;
                if (reg < 2) src = (reg ? g_x_lo : g_x_hi) + (size_t)s.toks[r] * DMODEL + k0 + j * 8;
                else         src = (reg == 3 ? g_k_lo : g_k_hi) + ((size_t)e * FEXP + n0 + r) * DMODEL + k0 + j * 8;
                pf[it] = *reinterpret_cast<const uint4*>(src);
            }
        }
        mma_stage(s, wm0, wn0, lane, acc);
    }

    const int g = lane >> 2, tc = (lane & 3) * 2;
    #pragma unroll
    for (int mt = 0; mt < 2; mt++)
        #pragma unroll
        for (int half = 0; half < 2; half++) {
            int mloc = wm0 + mt * 16 + half * 8 + g;
            if (m0 + mloc >= cnt) continue;
            float aff = s.affs[mloc];
            size_t rowb = ((size_t)e * TOKS + m0 + mloc) * FEXP;
            #pragma unroll
            for (int n8 = 0; n8 < 2; n8++) {
                int n = n0 + wn0 + n8 * 8 + tc;
                float v0 = acc[mt][n8][half * 2 + 0];
                float v1 = acc[mt][n8][half * 2 + 1];
                float h0 = v0 / (1.f + __expf(-v0)) * aff;
                float h1 = v1 / (1.f + __expf(-v1)) * aff;
                unsigned short hb0 = bf16bits(h0), hb1 = bf16bits(h1);
                unsigned short lb0 = bf16bits(h0 - bf16val(hb0));
                unsigned short lb1 = bf16bits(h1 - bf16val(hb1));
                *reinterpret_cast<uint32_t*>(reinterpret_cast<unsigned short*>(g_h_hi) + rowb + n)
                    = (uint32_t)hb0 | ((uint32_t)hb1 << 16);
                *reinterpret_cast<uint32_t*>(reinterpret_cast<unsigned short*>(g_h_lo) + rowb + n)
                    = (uint32_t)lb0 | ((uint32_t)lb1 << 16);
            }
        }
}

// ---------------- TC GEMM 2: g_out_tc[tok] += H @ V_e^T ---------------------
__global__ __launch_bounds__(256, 2) void moe_gemm2() {
    const int e   = blockIdx.y;
    const int cnt = g_cnt[e];
    const int m0  = blockIdx.x * BM;
    if (m0 >= cnt) return;
    const int n0  = blockIdx.z * BN;

    __shared__ GemmSmem s;
    const int tid = threadIdx.x, wid = tid >> 5, lane = tid & 31;
    const int wm0 = (wid & 1) * 32, wn0 = (wid >> 1) * 16;

    if (tid < BM) {
        int mg = m0 + tid;
        s.toks[tid] = (mg < cnt) ? g_tok[e * TOKS + mg] : 0;
    }
    __syncthreads();

    float acc[2][2][4];
    #pragma unroll
    for (int a = 0; a < 2; a++)
        #pragma unroll
        for (int b = 0; b < 2; b++)
            #pragma unroll
            for (int c = 0; c < 4; c++) acc[a][b][c] = 0.f;

    uint4 pf[8];
    #pragma unroll
    for (int it = 0; it < 8; it++) {
        int reg = it >> 1;
        int idx = tid + (it & 1) * 256;
        int r = idx >> 3, j = idx & 7;
        const __nv_bfloat16* src;
        if (reg < 2) src = (reg ? g_h_lo : g_h_hi) + ((size_t)e * TOKS + m0 + r) * FEXP + j * 8;
        else         src = (reg == 3 ? g_v_lo : g_v_hi) + ((size_t)e * DMODEL + n0 + r) * FEXP + j * 8;
        pf[it] = *reinterpret_cast<const uint4*>(src);
    }

    const int NC = FEXP / BK;    // 8
    for (int c = 0; c < NC; c++) {
        __syncthreads();
        store_stage(s, pf, tid);
        __syncthreads();
        if (c + 1 < NC) {
            int k0 = (c + 1) * BK;
            #pragma unroll
            for (int it = 0; it < 8; it++) {
                int reg = it >> 1;
                int idx = tid + (it & 1) * 256;
                int r = idx >> 3, j = idx & 7;
                const __nv_bfloat16* src;
                if (reg < 2) src = (reg ? g_h_lo : g_h_hi) + ((size_t)e * TOKS + m0 + r) * FEXP + k0 + j * 8;
                else         src = (reg == 3 ? g_v_lo : g_v_hi) + ((size_t)e * DMODEL + n0 + r) * FEXP + k0 + j * 8;
                pf[it] = *reinterpret_cast<const uint4*>(src);
            }
        }
        mma_stage(s, wm0, wn0, lane, acc);
    }

    const int g = lane >> 2, tc = (lane & 3) * 2;
    #pragma unroll
    for (int mt = 0; mt < 2; mt++)
        #pragma unroll
        for (int half = 0; half < 2; half++) {
            int mloc = wm0 + mt * 16 + half * 8 + g;
            if (m0 + mloc >= cnt) continue;
            float* dst = g_out_tc + (size_t)s.toks[mloc] * DMODEL;
            #pragma unroll
            for (int n8 = 0; n8 < 2; n8++) {
                int n = n0 + wn0 + n8 * 8 + tc;
                atomicAdd(dst + n + 0, acc[mt][n8][half * 2 + 0]);
                atomicAdd(dst + n + 1, acc[mt][n8][half * 2 + 1]);
            }
        }
}

// ---------------- end-to-end verify of TC path on 4 probe tokens ------------
__global__ __launch_bounds__(256) void verify_kernel(
    const float* __restrict__ x, const float* __restrict__ sel_in,
    const float* __restrict__ keys, const float* __restrict__ values,
    const float* __restrict__ expert_sel, const float* __restrict__ bias)
{
    const int t   = (blockIdx.x * 2731 + 17) & (TOKS - 1);
    const int tid = threadIdx.x;
    const int warp = tid >> 5, lane = tid & 31;
    __shared__ float logit[NEXP];
    __shared__ int   sel[KSEL];
    __shared__ float aff[KSEL];
    __shared__ float hbuf[FEXP];

    const float* xs = sel_in + (size_t)t * DMODEL;
    #pragma unroll
    for (int w = 0; w < 2; w++) {
        int e = warp * 2 + w;
        const float* wr = expert_sel + (size_t)e * DMODEL;
        float s = 0.f;
        for (int i = lane; i < DMODEL; i += 32) s += xs[i] * wr[i];
        #pragma unroll
        for (int o = 16; o > 0; o >>= 1) s += __shfl_xor_sync(0xffffffffu, s, o);
        if (lane == 0) logit[e] = s;
    }
    __syncthreads();

    if (tid == 0) {
        float a[NEXP];
        #pragma unroll
        for (int e = 0; e < NEXP; e++) a[e] = 1.f / (1.f + expf(-logit[e]));
        bool taken[NROUTED];
        #pragma unroll
        for (int i = 0; i < NROUTED; i++) taken[i] = false;
        #pragma unroll
        for (int k = 0; k < KROUTE; k++) {
            float best = -1e30f; int bi = 0;
            for (int i = 0; i < NROUTED; i++) {
                float v = a[i] + bias[i];
                if (!taken[i] && v > best) { best = v; bi = i; }
            }
            taken[bi] = true; sel[k] = bi; aff[k] = a[bi];
        }
        sel[4] = NROUTED;     aff[4] = a[NROUTED];
        sel[5] = NROUTED + 1; aff[5] = a[NROUTED + 1];
    }
    __syncthreads();

    const float* xt = x + (size_t)t * DMODEL;
    const int d = tid;                 // verify dims 0..255
    float acc = 0.f;
    for (int k = 0; k < KSEL; k++) {
        int e = sel[k];
        for (int f = tid; f < FEXP; f += 256) {
            float s = 0.f;
            const float* kw = keys + ((size_t)e * DMODEL) * FEXP + f;
            for (int kk = 0; kk < DMODEL; kk++) s += xt[kk] * kw[(size_t)kk * FEXP];
            hbuf[f] = s / (1.f + expf(-s)) * aff[k];
        }
        __syncthreads();
        float a2 = 0.f;
        const float* vw = values + ((size_t)e * FEXP) * DMODEL + d;
        for (int f = 0; f < FEXP; f++) a2 += hbuf[f] * vw[(size_t)f * DMODEL];
        acc += a2;
        __syncthreads();
    }

    float got = g_out_tc[(size_t)t * DMODEL + d];
    if (fabsf(got - acc) > 5e-4f * fmaxf(fabsf(acc), 0.5f)) g_ok = 0;
}

// ---------------- fp32 SIMT fallback GEMMs (round-1 proven) -----------------
__global__ __launch_bounds__(256) void fb_gemm1(
    const float* __restrict__ xs, const float* __restrict__ keys)
{
    if (g_ok) return;
    const int e   = blockIdx.y;
    const int cnt = g_cnt[e];
    const int m0  = blockIdx.x * 64;
    if (m0 >= cnt) return;
    const int n0  = blockIdx.z * 64;

    __shared__ float As[16][64];
    __shared__ float Bs[16][64];
    __shared__ int   toks[64];
    __shared__ float affs[64];

    const int tid = threadIdx.x;
    if (tid < 64) {
        int mg = m0 + tid;
        toks[tid] = (mg < cnt) ? g_tok[e * TOKS + mg] : 0;
        affs[tid] = (mg < cnt) ? g_aff[e * TOKS + mg] : 0.f;
    }
    __syncthreads();

    const int ty  = tid >> 4, tx  = tid & 15;
    const int am  = tid >> 2, akq = tid & 3;
    const int bk  = tid >> 4, bnq = tid & 15;
    const bool avalid = (m0 + am) < cnt;
    const float* arow = xs + (size_t)toks[am] * DMODEL;

    float acc[4][4];
    #pragma unroll
    for (int i = 0; i < 4; i++)
        #pragma unroll
        for (int j = 0; j < 4; j++) acc[i][j] = 0.f;

    for (int k0 = 0; k0 < DMODEL; k0 += 16) {
        float4 av = avalid ? *(const float4*)(arow + k0 + akq * 4)
                           : make_float4(0.f, 0.f, 0.f, 0.f);
        float4 bv = *(const float4*)(keys +
                    ((size_t)e * DMODEL + k0 + bk) * FEXP + n0 + bnq * 4);
        As[akq * 4 + 0][am] = av.x;
        As[akq * 4 + 1][am] = av.y;
        As[akq * 4 + 2][am] = av.z;
        As[akq * 4 + 3][am] = av.w;
        *(float4*)&Bs[bk][bnq * 4] = bv;
        __syncthreads();
        #pragma unroll
        for (int kk = 0; kk < 16; kk++) {
            float4 a = *(const float4*)&As[kk][ty * 4];
            float4 b = *(const float4*)&Bs[kk][tx * 4];
            float ar[4] = {a.x, a.y, a.z, a.w};
            float br[4] = {b.x, b.y, b.z, b.w};
            #pragma unroll
            for (int i = 0; i < 4; i++)
                #pragma unroll
                for (int j = 0; j < 4; j++) acc[i][j] += ar[i] * br[j];
        }
        __syncthreads();
    }

    const size_t hbase = ((size_t)e * TOKS + m0) * FEXP + n0;
    #pragma unroll
    for (int i = 0; i < 4; i++) {
        int m = ty * 4 + i;
        if (m0 + m < cnt) {
            float afv = affs[m];
            #pragma unroll
            for (int j = 0; j < 4; j++) {
                float v = acc[i][j];
                float s = v / (1.f + __expf(-v));
                g_hf[hbase + (size_t)m * FEXP + tx * 4 + j] = s * afv;
            }
        }
    }
}

__global__ __launch_bounds__(256) void fb_gemm2(
    const float* __restrict__ values, float* __restrict__ out)
{
    if (g_ok) return;
    const int e   = blockIdx.y;
    const int cnt = g_cnt[e];
    const int m0  = blockIdx.x * 64;
    if (m0 >= cnt) return;
    const int n0  = blockIdx.z * 64;

    __shared__ float As[16][64];
    __shared__ float Bs[16][64];
    __shared__ int   toks[64];

    const int tid = threadIdx.x;
    if (tid < 64) {
        int mg = m0 + tid;
        toks[tid] = (mg < cnt) ? g_tok[e * TOKS + mg] : 0;
    }
    __syncthreads();

    const int ty  = tid >> 4, tx  = tid & 15;
    const int am  = tid >> 2, akq = tid & 3;
    const int bk  = tid >> 4, bnq = tid & 15;
    const bool avalid = (m0 + am) < cnt;
    const float* arow = g_hf + ((size_t)e * TOKS + m0 + am) * FEXP;

    float acc[4][4];
    #pragma unroll
    for (int i = 0; i < 4; i++)
        #pragma unroll
        for (int j = 0; j < 4; j++) acc[i][j] = 0.f;

    for (int k0 = 0; k0 < FEXP; k0 += 16) {
        float4 av = avalid ? *(const float4*)(arow + k0 + akq * 4)
                           : make_float4(0.f, 0.f, 0.f, 0.f);
        float4 bv = *(const float4*)(values +
                    ((size_t)e * FEXP + k0 + bk) * DMODEL + n0 + bnq * 4);
        As[akq * 4 + 0][am] = av.x;
        As[akq * 4 + 1][am] = av.y;
        As[akq * 4 + 2][am] = av.z;
        As[akq * 4 + 3][am] = av.w;
        *(float4*)&Bs[bk][bnq * 4] = bv;
        __syncthreads();
        #pragma unroll
        for (int kk = 0; kk < 16; kk++) {
            float4 a = *(const float4*)&As[kk][ty * 4];
            float4 b = *(const float4*)&Bs[kk][tx * 4];
            float ar[4] = {a.x, a.y, a.z, a.w};
            float br[4] = {b.x, b.y, b.z, b.w};
            #pragma unroll
            for (int i = 0; i < 4; i++)
                #pragma unroll
                for (int j = 0; j < 4; j++) acc[i][j] += ar[i] * br[j];
        }
        __syncthreads();
    }

    #pragma unroll
    for (int i = 0; i < 4; i++) {
        int m = ty * 4 + i;
        if (m0 + m < cnt) {
            int t = toks[m];
            #pragma unroll
            for (int j = 0; j < 4; j++)
                atomicAdd(&out[(size_t)t * DMODEL + n0 + tx * 4 + j], acc[i][j]);
        }
    }
}

// ---------------- commit: copy TC result into out when verified -------------
__global__ void commit_kernel(float* __restrict__ out) {
    if (!g_ok) return;
    int i = blockIdx.x * blockDim.x + threadIdx.x;
    if (i < TOKS * DMODEL) out[i] = g_out_tc[i];
}

// ---------------- launch -----------------------------------------------------
extern "C" void kernel_launch(void* const* d_in, const int* in_sizes, int n_in,
                              void* d_out, int out_size) {
    const float* token_stream = (const float*)d_in[0];
    const float* sel_input    = (const float*)d_in[1];
    const float* keys         = (const float*)d_in[2];
    const float* values       = (const float*)d_in[3];
    const float* esel         = (const float*)d_in[4];
    const float* bias         = (const float*)d_in[5];
    float* out = (float*)d_out;

    const int write_sel = (out_size >= TOKS * DMODEL + TOKS * KSEL) ? 1 : 0;

    zero_out_kernel<<<(TOKS * DMODEL + 511) / 512, 512>>>(out, TOKS * DMODEL);
    zero_misc_kernel<<<1, 32>>>();
    zero_tc_kernel<<<(TOKS * DMODEL + 511) / 512, 512>>>();

    conv_x_kernel<<<(TOKS * DMODEL / 4 + 255) / 256, 256>>>(token_stream);
    dim3 tk(FEXP / 32, DMODEL / 32, NEXP);
    conv_tr_kernel<<<tk, dim3(32, 8)>>>(keys, g_k_hi, g_k_lo, DMODEL, FEXP);
    dim3 tv(DMODEL / 32, FEXP / 32, NEXP);
    conv_tr_kernel<<<tv, dim3(32, 8)>>>(values, g_v_hi, g_v_lo, FEXP, DMODEL);

    routing_kernel<<<TOKS, 256>>>(sel_input, esel, bias, out, write_sel);

    // tensor-core path into g_h / g_out_tc
    dim3 g1(TOKS / BM, NEXP, FEXP / BN);       // (128, 16, 8)
    moe_gemm1<<<g1, 256>>>();
    dim3 g2(TOKS / BM, NEXP, DMODEL / BN);     // (128, 16, 16)
    moe_gemm2<<<g2, 256>>>();

    // end-to-end verification of 4 probe tokens (dims 0..255)
    verify_kernel<<<4, 256>>>(token_stream, sel_input, keys, values, esel, bias);

    // fp32 fallback (early-returns when TC verified)
    dim3 f1(TOKS / 64, NEXP, FEXP / 64);
    fb_gemm1<<<f1, 256>>>(token_stream, keys);
    dim3 f2(TOKS / 64, NEXP, DMODEL / 64);
    fb_gemm2<<<f2, 256>>>(values, out);

    // commit TC result when verified
    commit_kernel<<<(TOKS * DMODEL + 511) / 512, 512>>>(out);
}